// round 2
// baseline (speedup 1.0000x reference)
#include <cuda_runtime.h>
#include <math.h>

// Problem constants
#define EMB   1024
#define NROWS 4096          // B * S
#define NH    16
#define HD    64
#define SEQ   1024
#define NB    4
#define NEGV  (-1e9f)

// Scratch (device globals: allocation-free, graph-capturable)
__device__ float g_P [2][(size_t)NROWS * EMB];   // proj outputs (pre-LN)
__device__ float g_QK[2][(size_t)NROWS * EMB];   // Q / K after LN+ReLU
__device__ float g_S [(size_t)NB * NH * SEQ * SEQ]; // scores, 256 MB

// ---------------------------------------------------------------------------
// Kernel 1: P = x @ W + b     (M=4096, N=1024, K=1024), 128x128x16 tiles
// blockIdx.z: 0 -> Wq, 1 -> Wk
// ---------------------------------------------------------------------------
__global__ __launch_bounds__(256) void proj_gemm(
    const float* __restrict__ X,
    const float* __restrict__ Wq, const float* __restrict__ bq,
    const float* __restrict__ Wk, const float* __restrict__ bk)
{
    const int which = blockIdx.z;
    const float* __restrict__ W    = which ? Wk : Wq;
    const float* __restrict__ bias = which ? bk : bq;
    float* __restrict__ P = g_P[which];

    __shared__ float As[16][128];
    __shared__ float Bs[16][128];

    const int m0 = blockIdx.y * 128;
    const int n0 = blockIdx.x * 128;
    const int tid = threadIdx.x;

    // A tile loads: 128 rows x 16 cols, thread -> (row, 8 cols)
    const int ar = tid >> 1;
    const int ac = (tid & 1) * 8;
    // B tile loads: 16 rows x 128 cols
    const int br = tid >> 4;
    const int bc = (tid & 15) * 8;
    // output microtile
    const int tm = (tid >> 4) * 8;
    const int tn = (tid & 15) * 8;

    const float* Ap = X + (size_t)(m0 + ar) * EMB + ac;
    const float* Bp = W + (size_t)br * EMB + n0 + bc;

    float acc[8][8];
#pragma unroll
    for (int i = 0; i < 8; i++)
#pragma unroll
        for (int j = 0; j < 8; j++) acc[i][j] = 0.f;

    for (int k0 = 0; k0 < EMB; k0 += 16) {
        float4 a0 = *(const float4*)(Ap + k0);
        float4 a1 = *(const float4*)(Ap + k0 + 4);
        float4 b0 = *(const float4*)(Bp + (size_t)k0 * EMB);
        float4 b1 = *(const float4*)(Bp + (size_t)k0 * EMB + 4);
        __syncthreads();
        As[ac + 0][ar] = a0.x; As[ac + 1][ar] = a0.y;
        As[ac + 2][ar] = a0.z; As[ac + 3][ar] = a0.w;
        As[ac + 4][ar] = a1.x; As[ac + 5][ar] = a1.y;
        As[ac + 6][ar] = a1.z; As[ac + 7][ar] = a1.w;
        *(float4*)&Bs[br][bc]     = b0;
        *(float4*)&Bs[br][bc + 4] = b1;
        __syncthreads();
#pragma unroll
        for (int kk = 0; kk < 16; kk++) {
            float ra[8], rb[8];
            *(float4*)(ra)     = *(const float4*)&As[kk][tm];
            *(float4*)(ra + 4) = *(const float4*)&As[kk][tm + 4];
            *(float4*)(rb)     = *(const float4*)&Bs[kk][tn];
            *(float4*)(rb + 4) = *(const float4*)&Bs[kk][tn + 4];
#pragma unroll
            for (int i = 0; i < 8; i++)
#pragma unroll
                for (int j = 0; j < 8; j++)
                    acc[i][j] = fmaf(ra[i], rb[j], acc[i][j]);
        }
    }

    float bb[8];
    *(float4*)(bb)     = *(const float4*)&bias[n0 + tn];
    *(float4*)(bb + 4) = *(const float4*)&bias[n0 + tn + 4];
#pragma unroll
    for (int i = 0; i < 8; i++) {
        float4 o0 = make_float4(acc[i][0] + bb[0], acc[i][1] + bb[1],
                                acc[i][2] + bb[2], acc[i][3] + bb[3]);
        float4 o1 = make_float4(acc[i][4] + bb[4], acc[i][5] + bb[5],
                                acc[i][6] + bb[6], acc[i][7] + bb[7]);
        size_t off = (size_t)(m0 + tm + i) * EMB + n0 + tn;
        *(float4*)&P[off]     = o0;
        *(float4*)&P[off + 4] = o1;
    }
}

// ---------------------------------------------------------------------------
// block reductions (256 threads)
// ---------------------------------------------------------------------------
template <bool IS_MAX>
__device__ __forceinline__ float block_reduce(float v)
{
    __shared__ float red[8];
    const int lane = threadIdx.x & 31;
    const int w    = threadIdx.x >> 5;
#pragma unroll
    for (int o = 16; o; o >>= 1) {
        float t = __shfl_xor_sync(0xffffffffu, v, o);
        v = IS_MAX ? fmaxf(v, t) : v + t;
    }
    if (lane == 0) red[w] = v;
    __syncthreads();
    if (w == 0) {
        float t2 = (lane < 8) ? red[lane] : (IS_MAX ? -3.4e38f : 0.f);
#pragma unroll
        for (int o = 4; o; o >>= 1) {
            float t = __shfl_xor_sync(0xffffffffu, t2, o);
            t2 = IS_MAX ? fmaxf(t2, t) : t2 + t;
        }
        if (lane == 0) red[0] = t2;
    }
    __syncthreads();
    float r = red[0];
    __syncthreads();
    return r;
}

// ---------------------------------------------------------------------------
// Kernel 2: LayerNorm + ReLU.  grid = (4096, 2), block = 256
// ---------------------------------------------------------------------------
__global__ __launch_bounds__(256) void ln_relu(
    const float* __restrict__ gq, const float* __restrict__ bqn,
    const float* __restrict__ gk, const float* __restrict__ bkn)
{
    const int row   = blockIdx.x;
    const int which = blockIdx.y;
    const int tid   = threadIdx.x;
    const float* __restrict__ gamma = which ? gk : gq;
    const float* __restrict__ beta  = which ? bkn : bqn;

    float4 v = ((const float4*)g_P[which])[(size_t)row * 256 + tid];
    float s  = v.x + v.y + v.z + v.w;
    float s2 = v.x * v.x + v.y * v.y + v.z * v.z + v.w * v.w;

    float S  = block_reduce<false>(s);
    float S2 = block_reduce<false>(s2);

    const float mu  = S * (1.f / EMB);
    const float var = S2 * (1.f / EMB) - mu * mu;
    const float rs  = rsqrtf(var + 1e-5f);

    const int c = tid * 4;
    float4 o;
    o.x = fmaxf((v.x - mu) * rs * gamma[c + 0] + beta[c + 0], 0.f);
    o.y = fmaxf((v.y - mu) * rs * gamma[c + 1] + beta[c + 1], 0.f);
    o.z = fmaxf((v.z - mu) * rs * gamma[c + 2] + beta[c + 2], 0.f);
    o.w = fmaxf((v.w - mu) * rs * gamma[c + 3] + beta[c + 3], 0.f);
    ((float4*)g_QK[which])[(size_t)row * 256 + tid] = o;
}

// ---------------------------------------------------------------------------
// Kernel 3: scores[b,h] = Q_h (1024x64) @ K_h^T (64x1024) * 1/8
// grid = (8 k-tiles, 8 q-tiles, 64 = b*16+h), 128x128 tile, inner D=64
// ---------------------------------------------------------------------------
__global__ __launch_bounds__(256) void score_gemm()
{
    const int kt = blockIdx.x;
    const int qt = blockIdx.y;
    const int bh = blockIdx.z;
    const int b  = bh >> 4;
    const int h  = bh & 15;

    const float* A  = g_QK[0] + ((size_t)(b * SEQ + qt * 128)) * EMB + h * HD;
    const float* Bm = g_QK[1] + ((size_t)(b * SEQ + kt * 128)) * EMB + h * HD;

    __shared__ float As[16][128];
    __shared__ float Bs[16][128];

    const int tid = threadIdx.x;
    const int ar  = tid >> 1;
    const int ac  = (tid & 1) * 8;
    const int tm  = (tid >> 4) * 8;
    const int tn  = (tid & 15) * 8;

    float acc[8][8];
#pragma unroll
    for (int i = 0; i < 8; i++)
#pragma unroll
        for (int j = 0; j < 8; j++) acc[i][j] = 0.f;

    const float* Ap = A  + (size_t)ar * EMB + ac;
    const float* Bp = Bm + (size_t)ar * EMB + ac;

    for (int k0 = 0; k0 < HD; k0 += 16) {
        float4 a0 = *(const float4*)(Ap + k0);
        float4 a1 = *(const float4*)(Ap + k0 + 4);
        float4 b0 = *(const float4*)(Bp + k0);
        float4 b1 = *(const float4*)(Bp + k0 + 4);
        __syncthreads();
        As[ac + 0][ar] = a0.x; As[ac + 1][ar] = a0.y;
        As[ac + 2][ar] = a0.z; As[ac + 3][ar] = a0.w;
        As[ac + 4][ar] = a1.x; As[ac + 5][ar] = a1.y;
        As[ac + 6][ar] = a1.z; As[ac + 7][ar] = a1.w;
        Bs[ac + 0][ar] = b0.x; Bs[ac + 1][ar] = b0.y;
        Bs[ac + 2][ar] = b0.z; Bs[ac + 3][ar] = b0.w;
        Bs[ac + 4][ar] = b1.x; Bs[ac + 5][ar] = b1.y;
        Bs[ac + 6][ar] = b1.z; Bs[ac + 7][ar] = b1.w;
        __syncthreads();
#pragma unroll
        for (int kk = 0; kk < 16; kk++) {
            float ra[8], rb[8];
            *(float4*)(ra)     = *(const float4*)&As[kk][tm];
            *(float4*)(ra + 4) = *(const float4*)&As[kk][tm + 4];
            *(float4*)(rb)     = *(const float4*)&Bs[kk][tn];
            *(float4*)(rb + 4) = *(const float4*)&Bs[kk][tn + 4];
#pragma unroll
            for (int i = 0; i < 8; i++)
#pragma unroll
                for (int j = 0; j < 8; j++)
                    acc[i][j] = fmaf(ra[i], rb[j], acc[i][j]);
        }
    }

    const float scale = 0.125f;  // 1/sqrt(64)
#pragma unroll
    for (int i = 0; i < 8; i++) {
        float4 o0 = make_float4(acc[i][0] * scale, acc[i][1] * scale,
                                acc[i][2] * scale, acc[i][3] * scale);
        float4 o1 = make_float4(acc[i][4] * scale, acc[i][5] * scale,
                                acc[i][6] * scale, acc[i][7] * scale);
        size_t off = ((size_t)bh * SEQ + qt * 128 + tm + i) * SEQ + kt * 128 + tn;
        *(float4*)&g_S[off]     = o0;
        *(float4*)&g_S[off + 4] = o1;
    }
}

// ---------------------------------------------------------------------------
// Kernel 4: symmetric mask + per-head softmax + mean over heads
// grid = (1024 q, 4 b), block = 256; each thread owns k = 4*tid .. 4*tid+3
// mask is int32 (bool converted by harness)
// ---------------------------------------------------------------------------
__global__ __launch_bounds__(256) void softmax_mean(
    const int* __restrict__ mask, float* __restrict__ out)
{
    const int q   = blockIdx.x;
    const int b   = blockIdx.y;
    const int tid = threadIdx.x;

    // mask row (coalesced, int4) | mask column (strided)
    const int* mrow = mask + ((size_t)(b * SEQ + q)) * SEQ;
    int4 mr = ((const int4*)mrow)[tid];
    const int kbase = tid * 4;
    int c0 = mask[((size_t)(b * SEQ + kbase + 0)) * SEQ + q];
    int c1 = mask[((size_t)(b * SEQ + kbase + 1)) * SEQ + q];
    int c2 = mask[((size_t)(b * SEQ + kbase + 2)) * SEQ + q];
    int c3 = mask[((size_t)(b * SEQ + kbase + 3)) * SEQ + q];
    const bool m0 = (mr.x | c0) != 0;
    const bool m1 = (mr.y | c1) != 0;
    const bool m2 = (mr.z | c2) != 0;
    const bool m3 = (mr.w | c3) != 0;

    float a0 = 0.f, a1 = 0.f, a2 = 0.f, a3 = 0.f;

    for (int h = 0; h < NH; h++) {
        const float4* Sp = (const float4*)(g_S + (((size_t)(b * NH + h) * SEQ + q) << 10));
        float4 s = Sp[tid];
        if (m0) s.x = NEGV;
        if (m1) s.y = NEGV;
        if (m2) s.z = NEGV;
        if (m3) s.w = NEGV;

        float mx = fmaxf(fmaxf(s.x, s.y), fmaxf(s.z, s.w));
        mx = block_reduce<true>(mx);

        float e0 = expf(s.x - mx);
        float e1 = expf(s.y - mx);
        float e2 = expf(s.z - mx);
        float e3 = expf(s.w - mx);

        float sm = block_reduce<false>(e0 + e1 + e2 + e3);
        float inv = 1.f / sm;
        a0 += e0 * inv; a1 += e1 * inv; a2 += e2 * inv; a3 += e3 * inv;
    }

    const float w = 1.f / (float)NH;
    float4 o = make_float4(a0 * w, a1 * w, a2 * w, a3 * w);
    ((float4*)out)[((size_t)(b * SEQ + q)) * 256 + tid] = o;
}

// ---------------------------------------------------------------------------
extern "C" void kernel_launch(void* const* d_in, const int* in_sizes, int n_in,
                              void* d_out, int out_size)
{
    const float* x    = (const float*)d_in[0];
    const int*   mask = (const int*)d_in[1];
    const float* Wq   = (const float*)d_in[2];
    const float* bq   = (const float*)d_in[3];
    const float* Wk   = (const float*)d_in[4];
    const float* bk   = (const float*)d_in[5];
    const float* gq   = (const float*)d_in[6];
    const float* bqn  = (const float*)d_in[7];
    const float* gk   = (const float*)d_in[8];
    const float* bkn  = (const float*)d_in[9];
    float* out = (float*)d_out;

    proj_gemm<<<dim3(8, 32, 2), 256>>>(x, Wq, bq, Wk, bk);
    ln_relu<<<dim3(4096, 2), 256>>>(gq, bqn, gk, bkn);
    score_gemm<<<dim3(8, 8, 64), 256>>>();
    softmax_mean<<<dim3(1024, 4), 256>>>(mask, out);
}

// round 4
// speedup vs baseline: 1.6308x; 1.6308x over previous
#include <cuda_runtime.h>
#include <cuda_bf16.h>
#include <math.h>
#include <stdint.h>

// Problem constants
#define EMB   1024
#define KEXP  3072          // 3x expanded K
#define NROWS 4096          // B * S
#define NH    16
#define HD    64
#define SEQ   1024
#define NB    4
#define NEGV  (-1e9f)

// Scratch (device globals: allocation-free, graph-capturable)
__device__ float          g_P [2][(size_t)NROWS * EMB];      // proj outputs (pre-LN)
__device__ __nv_bfloat16  g_xs [(size_t)NROWS * KEXP];       // x, A-pattern (h,h,l)
__device__ __nv_bfloat16  g_ws [2][(size_t)EMB * KEXP];      // W^T, B-pattern (h,l,h)
__device__ __nv_bfloat16  g_qs [2][(size_t)NROWS * KEXP];    // Q: A-pattern / K: B-pattern
__device__ float          g_S  [(size_t)NB * NH * SEQ * SEQ]; // scores, 256 MB

// ===========================================================================
// helpers
// ===========================================================================
__device__ __forceinline__ uint32_t smem_u32(const void* p) {
    uint32_t a;
    asm("{ .reg .u64 t; cvta.to.shared.u64 t, %1; cvt.u32.u64 %0, t; }"
        : "=r"(a) : "l"(p));
    return a;
}

#define CP16(s, g) \
    asm volatile("cp.async.cg.shared.global [%0], [%1], 16;" :: "r"(s), "l"(g))
#define CP_COMMIT() asm volatile("cp.async.commit_group;" ::: "memory")
#define CP_WAIT(n)  asm volatile("cp.async.wait_group %0;" :: "n"(n) : "memory")

__device__ __forceinline__ void ldsm4(uint32_t addr, uint32_t r[4]) {
    asm volatile("ldmatrix.sync.aligned.m8n8.x4.shared.b16 {%0,%1,%2,%3}, [%4];"
        : "=r"(r[0]), "=r"(r[1]), "=r"(r[2]), "=r"(r[3]) : "r"(addr));
}
__device__ __forceinline__ void mma16816(float c[4], const uint32_t a[4],
                                         uint32_t b0, uint32_t b1) {
    asm volatile(
        "mma.sync.aligned.m16n8k16.row.col.f32.bf16.bf16.f32 "
        "{%0,%1,%2,%3}, {%4,%5,%6,%7}, {%8,%9}, {%0,%1,%2,%3};"
        : "+f"(c[0]), "+f"(c[1]), "+f"(c[2]), "+f"(c[3])
        : "r"(a[0]), "r"(a[1]), "r"(a[2]), "r"(a[3]), "r"(b0), "r"(b1));
}

// ===========================================================================
// core 128x128 GEMM tile over expanded K (row stride KEXP for both operands)
// smem rows padded to 40 bf16 (80 B) -> conflict-free ldmatrix
// ===========================================================================
template <int KCHUNKS>
__device__ __forceinline__ void gemm_tile(
    const __nv_bfloat16* __restrict__ A,   // 128 rows, stride KEXP
    const __nv_bfloat16* __restrict__ B,   // 128 rows, stride KEXP
    float acc[2][8][4])
{
    __shared__ __nv_bfloat16 sm[2][2][128 * 40];
    const uint32_t sbase = smem_u32(&sm[0][0][0]);
    const int t = threadIdx.x, lane = t & 31, wid = t >> 5;
    const int wm = wid & 3, wn = wid >> 2;

    // cp.async per-thread slots: 2 x 16B per tile
    const int rA0 = t >> 2, cc = t & 3;
    const int rA1 = rA0 + 64;
    const uint32_t so0 = (uint32_t)(rA0 * 80 + cc * 16);
    const uint32_t so1 = (uint32_t)(rA1 * 80 + cc * 16);

    // ldmatrix per-thread byte offsets
    uint32_t aoff[2], boff[4];
#pragma unroll
    for (int mf = 0; mf < 2; mf++)
        aoff[mf] = (uint32_t)((wm * 32 + mf * 16 + (lane & 15)) * 80 + (lane >> 4) * 16);
#pragma unroll
    for (int g = 0; g < 4; g++)
        boff[g] = (uint32_t)((wn * 64 + g * 16 + (lane & 15)) * 80 + (lane >> 4) * 16);

    auto issue = [&](int buf, int c) {
        const uint32_t sA = sbase + (uint32_t)buf * 20480u;
        const uint32_t sB = sA + 10240u;
        const __nv_bfloat16* ga = A + c * 32;
        const __nv_bfloat16* gb = B + c * 32;
        CP16(sA + so0, ga + (size_t)rA0 * KEXP + cc * 8);
        CP16(sA + so1, ga + (size_t)rA1 * KEXP + cc * 8);
        CP16(sB + so0, gb + (size_t)rA0 * KEXP + cc * 8);
        CP16(sB + so1, gb + (size_t)rA1 * KEXP + cc * 8);
        CP_COMMIT();
    };

    issue(0, 0);
    for (int c = 0; c < KCHUNKS; c++) {
        const int buf = c & 1;
        if (c + 1 < KCHUNKS) { issue(buf ^ 1, c + 1); CP_WAIT(1); }
        else                 { CP_WAIT(0); }
        __syncthreads();
        const uint32_t sA = sbase + (uint32_t)buf * 20480u;
        const uint32_t sB = sA + 10240u;
#pragma unroll
        for (int ks = 0; ks < 2; ks++) {
            uint32_t a0[4], a1[4];
            ldsm4(sA + aoff[0] + ks * 32, a0);
            ldsm4(sA + aoff[1] + ks * 32, a1);
#pragma unroll
            for (int g = 0; g < 4; g++) {
                uint32_t bb[4];
                ldsm4(sB + boff[g] + ks * 32, bb);
                mma16816(acc[0][2 * g],     a0, bb[0], bb[2]);
                mma16816(acc[0][2 * g + 1], a0, bb[1], bb[3]);
                mma16816(acc[1][2 * g],     a1, bb[0], bb[2]);
                mma16816(acc[1][2 * g + 1], a1, bb[1], bb[3]);
            }
        }
        __syncthreads();
    }
}

// ===========================================================================
// Kernel A: split x -> A-pattern triplets (h,h,l)
// ===========================================================================
__global__ __launch_bounds__(256) void split_x(const float* __restrict__ x)
{
    size_t i = ((size_t)blockIdx.x * 256 + threadIdx.x) * 4;
    float4 v = *(const float4*)(x + i);
    float f[4] = {v.x, v.y, v.z, v.w};
    __nv_bfloat16 h[4], l[4];
#pragma unroll
    for (int j = 0; j < 4; j++) {
        h[j] = __float2bfloat16(f[j]);
        l[j] = __float2bfloat16(f[j] - __bfloat162float(h[j]));
    }
    __nv_bfloat162* o = (__nv_bfloat162*)(g_xs + i * 3);
    __nv_bfloat162 p;
    p.x = h[0]; p.y = h[0]; o[0] = p;
    p.x = l[0]; p.y = h[1]; o[1] = p;
    p.x = h[1]; p.y = l[1]; o[2] = p;
    p.x = h[2]; p.y = h[2]; o[3] = p;
    p.x = l[2]; p.y = h[3]; o[4] = p;
    p.x = h[3]; p.y = l[3]; o[5] = p;
}

// ===========================================================================
// Kernel B: transpose + split W -> W^T B-pattern triplets (h,l,h)
// grid (16,16,2), 64x64 tiles, 256 threads
// ===========================================================================
__global__ __launch_bounds__(256) void split_wt(
    const float* __restrict__ Wq, const float* __restrict__ Wk)
{
    __shared__ float t[64][65];
    const int which = blockIdx.z;
    const float* __restrict__ W = which ? Wk : Wq;
    const int n0 = blockIdx.x * 64, k0 = blockIdx.y * 64;
    const int c = threadIdx.x & 63, rb = threadIdx.x >> 6;

#pragma unroll
    for (int rr = 0; rr < 16; rr++) {
        int r = rb * 16 + rr;
        t[r][c] = W[(size_t)(k0 + r) * EMB + n0 + c];
    }
    __syncthreads();
#pragma unroll
    for (int rr = 0; rr < 16; rr++) {
        int r = rb * 16 + rr;          // local n index
        float v = t[c][r];             // W[k0+c][n0+r]
        __nv_bfloat16 h = __float2bfloat16(v);
        __nv_bfloat16 l = __float2bfloat16(v - __bfloat162float(h));
        size_t off = (size_t)(n0 + r) * KEXP + (size_t)(k0 + c) * 3;
        g_ws[which][off + 0] = h;
        g_ws[which][off + 1] = l;
        g_ws[which][off + 2] = h;
    }
}

// ===========================================================================
// Kernel C: projection GEMM, P = x @ W + b.  grid (8 N, 32 M, 2 which)
// ===========================================================================
__global__ __launch_bounds__(256) void proj_mma(
    const float* __restrict__ bq, const float* __restrict__ bk)
{
    const int n0 = blockIdx.x * 128, m0 = blockIdx.y * 128, which = blockIdx.z;
    const __nv_bfloat16* A = g_xs + (size_t)m0 * KEXP;
    const __nv_bfloat16* B = g_ws[which] + (size_t)n0 * KEXP;

    float acc[2][8][4] = {};
    gemm_tile<96>(A, B, acc);

    const float* __restrict__ bias = which ? bk : bq;
    float* __restrict__ P = g_P[which];
    const int lane = threadIdx.x & 31, wid = threadIdx.x >> 5;
    const int wm = wid & 3, wn = wid >> 2;

#pragma unroll
    for (int mf = 0; mf < 2; mf++) {
#pragma unroll
        for (int j = 0; j < 8; j++) {
            int row = m0 + wm * 32 + mf * 16 + (lane >> 2);
            int col = n0 + wn * 64 + j * 8 + (lane & 3) * 2;
            float b0 = bias[col], b1 = bias[col + 1];
            float2 o0 = make_float2(acc[mf][j][0] + b0, acc[mf][j][1] + b1);
            float2 o1 = make_float2(acc[mf][j][2] + b0, acc[mf][j][3] + b1);
            *(float2*)&P[(size_t)row * EMB + col]       = o0;
            *(float2*)&P[(size_t)(row + 8) * EMB + col] = o1;
        }
    }
}

// ---------------------------------------------------------------------------
// block reductions (256 threads)
// ---------------------------------------------------------------------------
template <bool IS_MAX>
__device__ __forceinline__ float block_reduce(float v)
{
    __shared__ float red[8];
    const int lane = threadIdx.x & 31;
    const int w    = threadIdx.x >> 5;
#pragma unroll
    for (int o = 16; o; o >>= 1) {
        float t = __shfl_xor_sync(0xffffffffu, v, o);
        v = IS_MAX ? fmaxf(v, t) : v + t;
    }
    if (lane == 0) red[w] = v;
    __syncthreads();
    if (w == 0) {
        float t2 = (lane < 8) ? red[lane] : (IS_MAX ? -3.4e38f : 0.f);
#pragma unroll
        for (int o = 4; o; o >>= 1) {
            float t = __shfl_xor_sync(0xffffffffu, t2, o);
            t2 = IS_MAX ? fmaxf(t2, t) : t2 + t;
        }
        if (lane == 0) red[0] = t2;
    }
    __syncthreads();
    float r = red[0];
    __syncthreads();
    return r;
}

// ---------------------------------------------------------------------------
// Kernel D: LayerNorm + ReLU -> split triplets.  grid (4096, 2), 256 threads
// which==0 (Q): A-pattern (h,h,l); which==1 (K): B-pattern (h,l,h)
// ---------------------------------------------------------------------------
__global__ __launch_bounds__(256) void ln_relu(
    const float* __restrict__ gq, const float* __restrict__ bqn,
    const float* __restrict__ gk, const float* __restrict__ bkn)
{
    const int row   = blockIdx.x;
    const int which = blockIdx.y;
    const int tid   = threadIdx.x;
    const float* __restrict__ gamma = which ? gk : gq;
    const float* __restrict__ beta  = which ? bkn : bqn;

    float4 v = ((const float4*)g_P[which])[(size_t)row * 256 + tid];
    float s  = v.x + v.y + v.z + v.w;
    float s2 = v.x * v.x + v.y * v.y + v.z * v.z + v.w * v.w;

    float S  = block_reduce<false>(s);
    float S2 = block_reduce<false>(s2);

    const float mu  = S * (1.f / EMB);
    const float var = S2 * (1.f / EMB) - mu * mu;
    const float rs  = rsqrtf(var + 1e-5f);

    const int c = tid * 4;
    float f[4];
    f[0] = fmaxf((v.x - mu) * rs * gamma[c + 0] + beta[c + 0], 0.f);
    f[1] = fmaxf((v.y - mu) * rs * gamma[c + 1] + beta[c + 1], 0.f);
    f[2] = fmaxf((v.z - mu) * rs * gamma[c + 2] + beta[c + 2], 0.f);
    f[3] = fmaxf((v.w - mu) * rs * gamma[c + 3] + beta[c + 3], 0.f);

    __nv_bfloat16 h[4], l[4];
#pragma unroll
    for (int j = 0; j < 4; j++) {
        h[j] = __float2bfloat16(f[j]);
        l[j] = __float2bfloat16(f[j] - __bfloat162float(h[j]));
    }

    __nv_bfloat162* o = (__nv_bfloat162*)(g_qs[which] + (size_t)row * KEXP + (size_t)c * 3);
    __nv_bfloat162 p;
    if (which == 0) {   // (h,h,l)
        p.x = h[0]; p.y = h[0]; o[0] = p;
        p.x = l[0]; p.y = h[1]; o[1] = p;
        p.x = h[1]; p.y = l[1]; o[2] = p;
        p.x = h[2]; p.y = h[2]; o[3] = p;
        p.x = l[2]; p.y = h[3]; o[4] = p;
        p.x = h[3]; p.y = l[3]; o[5] = p;
    } else {            // (h,l,h)
        p.x = h[0]; p.y = l[0]; o[0] = p;
        p.x = h[0]; p.y = h[1]; o[1] = p;
        p.x = l[1]; p.y = h[1]; o[2] = p;
        p.x = h[2]; p.y = l[2]; o[3] = p;
        p.x = h[2]; p.y = h[3]; o[4] = p;
        p.x = l[3]; p.y = h[3]; o[5] = p;
    }
}

// ===========================================================================
// Kernel E: score GEMM. S[b,h][q][k] = (Q_h . K_h)/8.  grid (8 kt, 8 qt, 64 bh)
// ===========================================================================
__global__ __launch_bounds__(256) void score_mma()
{
    const int kt = blockIdx.x, qt = blockIdx.y, bh = blockIdx.z;
    const int b = bh >> 4, h = bh & 15;

    const __nv_bfloat16* A = g_qs[0] + (size_t)(b * SEQ + qt * 128) * KEXP + h * HD * 3;
    const __nv_bfloat16* B = g_qs[1] + (size_t)(b * SEQ + kt * 128) * KEXP + h * HD * 3;

    float acc[2][8][4] = {};
    gemm_tile<6>(A, B, acc);

    const int lane = threadIdx.x & 31, wid = threadIdx.x >> 5;
    const int wm = wid & 3, wn = wid >> 2;

#pragma unroll
    for (int mf = 0; mf < 2; mf++) {
#pragma unroll
        for (int j = 0; j < 8; j++) {
            int q   = qt * 128 + wm * 32 + mf * 16 + (lane >> 2);
            int col = kt * 128 + wn * 64 + j * 8 + (lane & 3) * 2;
            float2 o0 = make_float2(acc[mf][j][0] * 0.125f, acc[mf][j][1] * 0.125f);
            float2 o1 = make_float2(acc[mf][j][2] * 0.125f, acc[mf][j][3] * 0.125f);
            float* S = g_S + ((size_t)bh * SEQ) * SEQ;
            *(float2*)&S[(size_t)q * SEQ + col]       = o0;
            *(float2*)&S[(size_t)(q + 8) * SEQ + col] = o1;
        }
    }
}

// ---------------------------------------------------------------------------
// Kernel F: symmetric mask + per-head softmax + mean over heads
// grid (1024 q, 4 b), block 256; mask is int32
// ---------------------------------------------------------------------------
__global__ __launch_bounds__(256) void softmax_mean(
    const int* __restrict__ mask, float* __restrict__ out)
{
    const int q   = blockIdx.x;
    const int b   = blockIdx.y;
    const int tid = threadIdx.x;

    const int* mrow = mask + ((size_t)(b * SEQ + q)) * SEQ;
    int4 mr = ((const int4*)mrow)[tid];
    const int kbase = tid * 4;
    int c0 = mask[((size_t)(b * SEQ + kbase + 0)) * SEQ + q];
    int c1 = mask[((size_t)(b * SEQ + kbase + 1)) * SEQ + q];
    int c2 = mask[((size_t)(b * SEQ + kbase + 2)) * SEQ + q];
    int c3 = mask[((size_t)(b * SEQ + kbase + 3)) * SEQ + q];
    const bool m0 = (mr.x | c0) != 0;
    const bool m1 = (mr.y | c1) != 0;
    const bool m2 = (mr.z | c2) != 0;
    const bool m3 = (mr.w | c3) != 0;

    float a0 = 0.f, a1 = 0.f, a2 = 0.f, a3 = 0.f;

    for (int h = 0; h < NH; h++) {
        const float4* Sp = (const float4*)(g_S + (((size_t)(b * NH + h) * SEQ + q) << 10));
        float4 s = Sp[tid];
        if (m0) s.x = NEGV;
        if (m1) s.y = NEGV;
        if (m2) s.z = NEGV;
        if (m3) s.w = NEGV;

        float mx = fmaxf(fmaxf(s.x, s.y), fmaxf(s.z, s.w));
        mx = block_reduce<true>(mx);

        float e0 = expf(s.x - mx);
        float e1 = expf(s.y - mx);
        float e2 = expf(s.z - mx);
        float e3 = expf(s.w - mx);

        float sm = block_reduce<false>(e0 + e1 + e2 + e3);
        float inv = 1.f / sm;
        a0 += e0 * inv; a1 += e1 * inv; a2 += e2 * inv; a3 += e3 * inv;
    }

    const float w = 1.f / (float)NH;
    float4 o = make_float4(a0 * w, a1 * w, a2 * w, a3 * w);
    ((float4*)out)[((size_t)(b * SEQ + q)) * 256 + tid] = o;
}

// ---------------------------------------------------------------------------
extern "C" void kernel_launch(void* const* d_in, const int* in_sizes, int n_in,
                              void* d_out, int out_size)
{
    const float* x    = (const float*)d_in[0];
    const int*   mask = (const int*)d_in[1];
    const float* Wq   = (const float*)d_in[2];
    const float* bq   = (const float*)d_in[3];
    const float* Wk   = (const float*)d_in[4];
    const float* bk   = (const float*)d_in[5];
    const float* gq   = (const float*)d_in[6];
    const float* bqn  = (const float*)d_in[7];
    const float* gk   = (const float*)d_in[8];
    const float* bkn  = (const float*)d_in[9];
    float* out = (float*)d_out;

    split_x <<<4096, 256>>>(x);
    split_wt<<<dim3(16, 16, 2), 256>>>(Wq, Wk);
    proj_mma<<<dim3(8, 32, 2), 256>>>(bq, bk);
    ln_relu <<<dim3(4096, 2), 256>>>(gq, bqn, gk, bkn);
    score_mma<<<dim3(8, 8, 64), 256>>>();
    softmax_mean<<<dim3(1024, 4), 256>>>(mask, out);
}

// round 5
// speedup vs baseline: 1.7261x; 1.0584x over previous
#include <cuda_runtime.h>
#include <cuda_bf16.h>
#include <math.h>
#include <stdint.h>

// Problem constants
#define EMB   1024
#define KEXP  3072          // 3x expanded K
#define NROWS 4096          // B * S
#define NH    16
#define HD    64
#define SEQ   1024
#define NB    4
#define NEGV  (-1e9f)

// Scratch (device globals: allocation-free, graph-capturable)
__device__ float          g_P [2][(size_t)NROWS * EMB];      // proj outputs (pre-LN)
__device__ __nv_bfloat16  g_xs [(size_t)NROWS * KEXP];       // x, A-pattern (h,h,l)
__device__ __nv_bfloat16  g_ws [2][(size_t)EMB * KEXP];      // W^T, B-pattern (h,l,h)
__device__ __nv_bfloat16  g_qs [2][(size_t)NROWS * KEXP];    // Q: A-pattern / K: B-pattern
__device__ float          g_S  [(size_t)NB * NH * SEQ * SEQ]; // scores, 256 MB
__device__ unsigned char  g_M  [(size_t)NB * SEQ * SEQ];     // symmetric mask, 4 MB

// ===========================================================================
// helpers
// ===========================================================================
__device__ __forceinline__ uint32_t smem_u32(const void* p) {
    uint32_t a;
    asm("{ .reg .u64 t; cvta.to.shared.u64 t, %1; cvt.u32.u64 %0, t; }"
        : "=r"(a) : "l"(p));
    return a;
}

#define CP16(s, g) \
    asm volatile("cp.async.cg.shared.global [%0], [%1], 16;" :: "r"(s), "l"(g))
#define CP_COMMIT() asm volatile("cp.async.commit_group;" ::: "memory")
#define CP_WAIT(n)  asm volatile("cp.async.wait_group %0;" :: "n"(n) : "memory")

__device__ __forceinline__ void ldsm4(uint32_t addr, uint32_t r[4]) {
    asm volatile("ldmatrix.sync.aligned.m8n8.x4.shared.b16 {%0,%1,%2,%3}, [%4];"
        : "=r"(r[0]), "=r"(r[1]), "=r"(r[2]), "=r"(r[3]) : "r"(addr));
}
__device__ __forceinline__ void mma16816(float c[4], const uint32_t a[4],
                                         uint32_t b0, uint32_t b1) {
    asm volatile(
        "mma.sync.aligned.m16n8k16.row.col.f32.bf16.bf16.f32 "
        "{%0,%1,%2,%3}, {%4,%5,%6,%7}, {%8,%9}, {%0,%1,%2,%3};"
        : "+f"(c[0]), "+f"(c[1]), "+f"(c[2]), "+f"(c[3])
        : "r"(a[0]), "r"(a[1]), "r"(a[2]), "r"(a[3]), "r"(b0), "r"(b1));
}

// ===========================================================================
// core 128x128 GEMM tile over expanded K (row stride KEXP for both operands)
// smem rows padded to 40 bf16 (80 B) -> conflict-free ldmatrix
// ===========================================================================
template <int KCHUNKS>
__device__ __forceinline__ void gemm_tile(
    const __nv_bfloat16* __restrict__ A,   // 128 rows, stride KEXP
    const __nv_bfloat16* __restrict__ B,   // 128 rows, stride KEXP
    float acc[2][8][4])
{
    __shared__ __nv_bfloat16 sm[2][2][128 * 40];
    const uint32_t sbase = smem_u32(&sm[0][0][0]);
    const int t = threadIdx.x, lane = t & 31, wid = t >> 5;
    const int wm = wid & 3, wn = wid >> 2;

    // cp.async per-thread slots: 2 x 16B per tile
    const int rA0 = t >> 2, cc = t & 3;
    const int rA1 = rA0 + 64;
    const uint32_t so0 = (uint32_t)(rA0 * 80 + cc * 16);
    const uint32_t so1 = (uint32_t)(rA1 * 80 + cc * 16);

    // ldmatrix per-thread byte offsets
    uint32_t aoff[2], boff[4];
#pragma unroll
    for (int mf = 0; mf < 2; mf++)
        aoff[mf] = (uint32_t)((wm * 32 + mf * 16 + (lane & 15)) * 80 + (lane >> 4) * 16);
#pragma unroll
    for (int g = 0; g < 4; g++)
        boff[g] = (uint32_t)((wn * 64 + g * 16 + (lane & 15)) * 80 + (lane >> 4) * 16);

    auto issue = [&](int buf, int c) {
        const uint32_t sA = sbase + (uint32_t)buf * 20480u;
        const uint32_t sB = sA + 10240u;
        const __nv_bfloat16* ga = A + c * 32;
        const __nv_bfloat16* gb = B + c * 32;
        CP16(sA + so0, ga + (size_t)rA0 * KEXP + cc * 8);
        CP16(sA + so1, ga + (size_t)rA1 * KEXP + cc * 8);
        CP16(sB + so0, gb + (size_t)rA0 * KEXP + cc * 8);
        CP16(sB + so1, gb + (size_t)rA1 * KEXP + cc * 8);
        CP_COMMIT();
    };

    issue(0, 0);
    for (int c = 0; c < KCHUNKS; c++) {
        const int buf = c & 1;
        if (c + 1 < KCHUNKS) { issue(buf ^ 1, c + 1); CP_WAIT(1); }
        else                 { CP_WAIT(0); }
        __syncthreads();
        const uint32_t sA = sbase + (uint32_t)buf * 20480u;
        const uint32_t sB = sA + 10240u;
#pragma unroll
        for (int ks = 0; ks < 2; ks++) {
            uint32_t a0[4], a1[4];
            ldsm4(sA + aoff[0] + ks * 32, a0);
            ldsm4(sA + aoff[1] + ks * 32, a1);
#pragma unroll
            for (int g = 0; g < 4; g++) {
                uint32_t bb[4];
                ldsm4(sB + boff[g] + ks * 32, bb);
                mma16816(acc[0][2 * g],     a0, bb[0], bb[2]);
                mma16816(acc[0][2 * g + 1], a0, bb[1], bb[3]);
                mma16816(acc[1][2 * g],     a1, bb[0], bb[2]);
                mma16816(acc[1][2 * g + 1], a1, bb[1], bb[3]);
            }
        }
        __syncthreads();
    }
}

// ===========================================================================
// Kernel A: split x -> A-pattern triplets (h,h,l)
// ===========================================================================
__global__ __launch_bounds__(256) void split_x(const float* __restrict__ x)
{
    size_t i = ((size_t)blockIdx.x * 256 + threadIdx.x) * 4;
    float4 v = *(const float4*)(x + i);
    float f[4] = {v.x, v.y, v.z, v.w};
    __nv_bfloat16 h[4], l[4];
#pragma unroll
    for (int j = 0; j < 4; j++) {
        h[j] = __float2bfloat16(f[j]);
        l[j] = __float2bfloat16(f[j] - __bfloat162float(h[j]));
    }
    __nv_bfloat162* o = (__nv_bfloat162*)(g_xs + i * 3);
    __nv_bfloat162 p;
    p.x = h[0]; p.y = h[0]; o[0] = p;
    p.x = l[0]; p.y = h[1]; o[1] = p;
    p.x = h[1]; p.y = l[1]; o[2] = p;
    p.x = h[2]; p.y = h[2]; o[3] = p;
    p.x = l[2]; p.y = h[3]; o[4] = p;
    p.x = h[3]; p.y = l[3]; o[5] = p;
}

// ===========================================================================
// Kernel B: transpose + split W -> W^T B-pattern triplets (h,l,h)
// grid (16,16,2), 64x64 tiles, 256 threads
// ===========================================================================
__global__ __launch_bounds__(256) void split_wt(
    const float* __restrict__ Wq, const float* __restrict__ Wk)
{
    __shared__ float t[64][65];
    const int which = blockIdx.z;
    const float* __restrict__ W = which ? Wk : Wq;
    const int n0 = blockIdx.x * 64, k0 = blockIdx.y * 64;
    const int c = threadIdx.x & 63, rb = threadIdx.x >> 6;

#pragma unroll
    for (int rr = 0; rr < 16; rr++) {
        int r = rb * 16 + rr;
        t[r][c] = W[(size_t)(k0 + r) * EMB + n0 + c];
    }
    __syncthreads();
#pragma unroll
    for (int rr = 0; rr < 16; rr++) {
        int r = rb * 16 + rr;          // local n index
        float v = t[c][r];             // W[k0+c][n0+r]
        __nv_bfloat16 h = __float2bfloat16(v);
        __nv_bfloat16 l = __float2bfloat16(v - __bfloat162float(h));
        size_t off = (size_t)(n0 + r) * KEXP + (size_t)(k0 + c) * 3;
        g_ws[which][off + 0] = h;
        g_ws[which][off + 1] = l;
        g_ws[which][off + 2] = h;
    }
}

// ===========================================================================
// Kernel B2: symmetric mask.  M[b][q][k] = mask[b][q][k] | mask[b][k][q]
// grid (32, 32, 4), 256 threads; 32x32 int tiles, packed uchar out
// ===========================================================================
__global__ __launch_bounds__(256) void mask_or(const int* __restrict__ mask)
{
    __shared__ int tB[32][33];
    const int b  = blockIdx.z;
    const int q0 = blockIdx.y * 32;
    const int k0 = blockIdx.x * 32;
    const int r  = threadIdx.x >> 3;          // 0..31
    const int c4 = (threadIdx.x & 7) * 4;     // 0,4,..,28

    // transposed-source tile: tB[r][c] = mask[b][k0+r][q0+c]
    int4 tb = *(const int4*)&mask[((size_t)(b * SEQ + k0 + r)) * SEQ + q0 + c4];
    tB[r][c4 + 0] = tb.x; tB[r][c4 + 1] = tb.y;
    tB[r][c4 + 2] = tb.z; tB[r][c4 + 3] = tb.w;
    __syncthreads();

    int4 a = *(const int4*)&mask[((size_t)(b * SEQ + q0 + r)) * SEQ + k0 + c4];
    uchar4 o;
    o.x = (a.x | tB[c4 + 0][r]) ? 1 : 0;
    o.y = (a.y | tB[c4 + 1][r]) ? 1 : 0;
    o.z = (a.z | tB[c4 + 2][r]) ? 1 : 0;
    o.w = (a.w | tB[c4 + 3][r]) ? 1 : 0;
    *(uchar4*)&g_M[((size_t)(b * SEQ + q0 + r)) * SEQ + k0 + c4] = o;
}

// ===========================================================================
// Kernel C: projection GEMM, P = x @ W + b.  grid (8 N, 32 M, 2 which)
// ===========================================================================
__global__ __launch_bounds__(256) void proj_mma(
    const float* __restrict__ bq, const float* __restrict__ bk)
{
    const int n0 = blockIdx.x * 128, m0 = blockIdx.y * 128, which = blockIdx.z;
    const __nv_bfloat16* A = g_xs + (size_t)m0 * KEXP;
    const __nv_bfloat16* B = g_ws[which] + (size_t)n0 * KEXP;

    float acc[2][8][4] = {};
    gemm_tile<96>(A, B, acc);

    const float* __restrict__ bias = which ? bk : bq;
    float* __restrict__ P = g_P[which];
    const int lane = threadIdx.x & 31, wid = threadIdx.x >> 5;
    const int wm = wid & 3, wn = wid >> 2;

#pragma unroll
    for (int mf = 0; mf < 2; mf++) {
#pragma unroll
        for (int j = 0; j < 8; j++) {
            int row = m0 + wm * 32 + mf * 16 + (lane >> 2);
            int col = n0 + wn * 64 + j * 8 + (lane & 3) * 2;
            float b0 = bias[col], b1 = bias[col + 1];
            float2 o0 = make_float2(acc[mf][j][0] + b0, acc[mf][j][1] + b1);
            float2 o1 = make_float2(acc[mf][j][2] + b0, acc[mf][j][3] + b1);
            *(float2*)&P[(size_t)row * EMB + col]       = o0;
            *(float2*)&P[(size_t)(row + 8) * EMB + col] = o1;
        }
    }
}

// ---------------------------------------------------------------------------
// fused pair block reduction (sum), 256 threads, 2 barriers
// ---------------------------------------------------------------------------
__device__ __forceinline__ float2 block_reduce_pair(float a, float b)
{
    __shared__ float red[8][2];
    const int lane = threadIdx.x & 31;
    const int w    = threadIdx.x >> 5;
#pragma unroll
    for (int o = 16; o; o >>= 1) {
        a += __shfl_xor_sync(0xffffffffu, a, o);
        b += __shfl_xor_sync(0xffffffffu, b, o);
    }
    if (lane == 0) { red[w][0] = a; red[w][1] = b; }
    __syncthreads();
    if (w == 0) {
        float x = (lane < 8) ? red[lane][0] : 0.f;
        float y = (lane < 8) ? red[lane][1] : 0.f;
#pragma unroll
        for (int o = 4; o; o >>= 1) {
            x += __shfl_xor_sync(0xffffffffu, x, o);
            y += __shfl_xor_sync(0xffffffffu, y, o);
        }
        if (lane == 0) { red[0][0] = x; red[0][1] = y; }
    }
    __syncthreads();
    return make_float2(red[0][0], red[0][1]);
}

// ---------------------------------------------------------------------------
// Kernel D: LayerNorm + ReLU -> split triplets.  grid (4096, 2), 256 threads
// which==0 (Q): A-pattern (h,h,l); which==1 (K): B-pattern (h,l,h)
// ---------------------------------------------------------------------------
__global__ __launch_bounds__(256) void ln_relu(
    const float* __restrict__ gq, const float* __restrict__ bqn,
    const float* __restrict__ gk, const float* __restrict__ bkn)
{
    const int row   = blockIdx.x;
    const int which = blockIdx.y;
    const int tid   = threadIdx.x;
    const float* __restrict__ gamma = which ? gk : gq;
    const float* __restrict__ beta  = which ? bkn : bqn;

    float4 v = ((const float4*)g_P[which])[(size_t)row * 256 + tid];
    float s  = v.x + v.y + v.z + v.w;
    float s2 = v.x * v.x + v.y * v.y + v.z * v.z + v.w * v.w;

    float2 SS = block_reduce_pair(s, s2);

    const float mu  = SS.x * (1.f / EMB);
    const float var = SS.y * (1.f / EMB) - mu * mu;
    const float rs  = rsqrtf(var + 1e-5f);

    const int c = tid * 4;
    float f[4];
    f[0] = fmaxf((v.x - mu) * rs * gamma[c + 0] + beta[c + 0], 0.f);
    f[1] = fmaxf((v.y - mu) * rs * gamma[c + 1] + beta[c + 1], 0.f);
    f[2] = fmaxf((v.z - mu) * rs * gamma[c + 2] + beta[c + 2], 0.f);
    f[3] = fmaxf((v.w - mu) * rs * gamma[c + 3] + beta[c + 3], 0.f);

    __nv_bfloat16 h[4], l[4];
#pragma unroll
    for (int j = 0; j < 4; j++) {
        h[j] = __float2bfloat16(f[j]);
        l[j] = __float2bfloat16(f[j] - __bfloat162float(h[j]));
    }

    __nv_bfloat162* o = (__nv_bfloat162*)(g_qs[which] + (size_t)row * KEXP + (size_t)c * 3);
    __nv_bfloat162 p;
    if (which == 0) {   // (h,h,l)
        p.x = h[0]; p.y = h[0]; o[0] = p;
        p.x = l[0]; p.y = h[1]; o[1] = p;
        p.x = h[1]; p.y = l[1]; o[2] = p;
        p.x = h[2]; p.y = h[2]; o[3] = p;
        p.x = l[2]; p.y = h[3]; o[4] = p;
        p.x = h[3]; p.y = l[3]; o[5] = p;
    } else {            // (h,l,h)
        p.x = h[0]; p.y = l[0]; o[0] = p;
        p.x = h[0]; p.y = h[1]; o[1] = p;
        p.x = l[1]; p.y = h[1]; o[2] = p;
        p.x = h[2]; p.y = l[2]; o[3] = p;
        p.x = h[2]; p.y = h[3]; o[4] = p;
        p.x = l[3]; p.y = h[3]; o[5] = p;
    }
}

// ===========================================================================
// Kernel E: score GEMM. S[b,h][q][k] = (Q_h . K_h)/8.  grid (8 kt, 8 qt, 64 bh)
// ===========================================================================
__global__ __launch_bounds__(256) void score_mma()
{
    const int kt = blockIdx.x, qt = blockIdx.y, bh = blockIdx.z;
    const int b = bh >> 4, h = bh & 15;

    const __nv_bfloat16* A = g_qs[0] + (size_t)(b * SEQ + qt * 128) * KEXP + h * HD * 3;
    const __nv_bfloat16* B = g_qs[1] + (size_t)(b * SEQ + kt * 128) * KEXP + h * HD * 3;

    float acc[2][8][4] = {};
    gemm_tile<6>(A, B, acc);

    const int lane = threadIdx.x & 31, wid = threadIdx.x >> 5;
    const int wm = wid & 3, wn = wid >> 2;

#pragma unroll
    for (int mf = 0; mf < 2; mf++) {
#pragma unroll
        for (int j = 0; j < 8; j++) {
            int q   = qt * 128 + wm * 32 + mf * 16 + (lane >> 2);
            int col = kt * 128 + wn * 64 + j * 8 + (lane & 3) * 2;
            float2 o0 = make_float2(acc[mf][j][0] * 0.125f, acc[mf][j][1] * 0.125f);
            float2 o1 = make_float2(acc[mf][j][2] * 0.125f, acc[mf][j][3] * 0.125f);
            float* S = g_S + ((size_t)bh * SEQ) * SEQ;
            *(float2*)&S[(size_t)q * SEQ + col]       = o0;
            *(float2*)&S[(size_t)(q + 8) * SEQ + col] = o1;
        }
    }
}

// ---------------------------------------------------------------------------
// Kernel F: symmetric mask + per-head softmax + mean over heads
// grid (1024 q, 4 b), 256 threads; thread owns k = 4*tid .. 4*tid+3
// All 16 heads resident in registers; batched reductions (5 barriers total).
// ---------------------------------------------------------------------------
__global__ __launch_bounds__(256, 2) void softmax_mean(float* __restrict__ out)
{
    __shared__ float sred[16][8];
    __shared__ float gmaxv[16];
    __shared__ float gsumv[16];
    __shared__ float rinv[16];

    const int q    = blockIdx.x;
    const int b    = blockIdx.y;
    const int tid  = threadIdx.x;
    const int lane = tid & 31;
    const int wid  = tid >> 5;

    uchar4 mb = ((const uchar4*)(g_M + ((size_t)(b * SEQ + q)) * SEQ))[tid];
    const bool m0 = mb.x, m1 = mb.y, m2 = mb.z, m3 = mb.w;

    // load all 16 head rows into registers, apply mask, per-thread max
    float sc[16][4];
    float tval[16];
#pragma unroll
    for (int h = 0; h < NH; h++) {
        const float4* Sp = (const float4*)(g_S + (((size_t)(b * NH + h) * SEQ + q) << 10));
        float4 s = Sp[tid];
        sc[h][0] = m0 ? NEGV : s.x;
        sc[h][1] = m1 ? NEGV : s.y;
        sc[h][2] = m2 ? NEGV : s.z;
        sc[h][3] = m3 ? NEGV : s.w;
        tval[h] = fmaxf(fmaxf(sc[h][0], sc[h][1]), fmaxf(sc[h][2], sc[h][3]));
    }

    // batched max reduction: warp shuffles then one smem combine for all heads
#pragma unroll
    for (int h = 0; h < NH; h++) {
        float v = tval[h];
#pragma unroll
        for (int o = 16; o; o >>= 1) v = fmaxf(v, __shfl_xor_sync(0xffffffffu, v, o));
        if (lane == h) sred[h][wid] = v;
    }
    __syncthreads();
    if (tid < 128) {
        const int h = tid >> 3, j = tid & 7;
        float v = sred[h][j];
        v = fmaxf(v, __shfl_xor_sync(0xffffffffu, v, 4, 8));
        v = fmaxf(v, __shfl_xor_sync(0xffffffffu, v, 2, 8));
        v = fmaxf(v, __shfl_xor_sync(0xffffffffu, v, 1, 8));
        if (j == 0) gmaxv[h] = v;
    }
    __syncthreads();

    // exp + batched sum reduction
#pragma unroll
    for (int h = 0; h < NH; h++) {
        const float gm = gmaxv[h];
        sc[h][0] = __expf(sc[h][0] - gm);
        sc[h][1] = __expf(sc[h][1] - gm);
        sc[h][2] = __expf(sc[h][2] - gm);
        sc[h][3] = __expf(sc[h][3] - gm);
        tval[h] = (sc[h][0] + sc[h][1]) + (sc[h][2] + sc[h][3]);
    }
#pragma unroll
    for (int h = 0; h < NH; h++) {
        float v = tval[h];
#pragma unroll
        for (int o = 16; o; o >>= 1) v += __shfl_xor_sync(0xffffffffu, v, o);
        if (lane == h) sred[h][wid] = v;
    }
    __syncthreads();
    if (tid < 128) {
        const int h = tid >> 3, j = tid & 7;
        float v = sred[h][j];
        v += __shfl_xor_sync(0xffffffffu, v, 4, 8);
        v += __shfl_xor_sync(0xffffffffu, v, 2, 8);
        v += __shfl_xor_sync(0xffffffffu, v, 1, 8);
        if (j == 0) gsumv[h] = v;
    }
    __syncthreads();
    if (tid < 16) rinv[tid] = 1.f / gsumv[tid];
    __syncthreads();

    float a0 = 0.f, a1 = 0.f, a2 = 0.f, a3 = 0.f;
#pragma unroll
    for (int h = 0; h < NH; h++) {
        const float iv = rinv[h];
        a0 = fmaf(sc[h][0], iv, a0);
        a1 = fmaf(sc[h][1], iv, a1);
        a2 = fmaf(sc[h][2], iv, a2);
        a3 = fmaf(sc[h][3], iv, a3);
    }
    const float w = 1.f / (float)NH;
    float4 o = make_float4(a0 * w, a1 * w, a2 * w, a3 * w);
    ((float4*)out)[((size_t)(b * SEQ + q)) * 256 + tid] = o;
}

// ---------------------------------------------------------------------------
extern "C" void kernel_launch(void* const* d_in, const int* in_sizes, int n_in,
                              void* d_out, int out_size)
{
    const float* x    = (const float*)d_in[0];
    const int*   mask = (const int*)d_in[1];
    const float* Wq   = (const float*)d_in[2];
    const float* bq   = (const float*)d_in[3];
    const float* Wk   = (const float*)d_in[4];
    const float* bk   = (const float*)d_in[5];
    const float* gq   = (const float*)d_in[6];
    const float* bqn  = (const float*)d_in[7];
    const float* gk   = (const float*)d_in[8];
    const float* bkn  = (const float*)d_in[9];
    float* out = (float*)d_out;

    split_x <<<4096, 256>>>(x);
    split_wt<<<dim3(16, 16, 2), 256>>>(Wq, Wk);
    mask_or <<<dim3(32, 32, 4), 256>>>(mask);
    proj_mma<<<dim3(8, 32, 2), 256>>>(bq, bk);
    ln_relu <<<dim3(4096, 2), 256>>>(gq, bqn, gk, bkn);
    score_mma<<<dim3(8, 8, 64), 256>>>();
    softmax_mean<<<dim3(1024, 4), 256>>>(out);
}